// round 8
// baseline (speedup 1.0000x reference)
#include <cuda_runtime.h>

#define THREADS 128   // one row per CTA: 4 warps, each lane owns 8 complex pts

// ===================== compile-time twiddle table =======================
// TW[k*32 + n] = exp(-2*pi*i * n*k / 1024), n,k in [0,32).
__host__ __device__ constexpr double tsin_(double x) {
    double t = x, s = x;
    for (int k = 1; k < 13; k++) { t *= -x * x / ((2.0 * k) * (2.0 * k + 1.0)); s += t; }
    return s;
}
__host__ __device__ constexpr double tcos_(double x) {
    double t = 1.0, s = 1.0;
    for (int k = 1; k < 13; k++) { t *= -x * x / ((2.0 * k - 1.0) * (2.0 * k)); s += t; }
    return s;
}
struct alignas(16) TwTab { float2 v[1024]; };
__host__ __device__ constexpr TwTab make_tw_() {
    TwTab t{};
    constexpr double PI = 3.14159265358979323846;
    for (int k = 0; k < 32; k++)
        for (int n = 0; n < 32; n++) {
            double ang = -2.0 * PI * (double)(n * k) / 1024.0;
            if (ang < -PI) ang += 2.0 * PI;
            t.v[k * 32 + n] = float2{ (float)tcos_(ang), (float)tsin_(ang) };
        }
    return t;
}
__device__ const TwTab TW = make_tw_();

__device__ __forceinline__ void cmul_v(float& rr, float& ri,
                                       float ar, float ai, float br, float bi) {
    rr = fmaf(ar, br, -ai * bi);
    ri = fmaf(ar, bi,  ai * br);
}

__device__ __forceinline__ int br3(int j) {
    return ((j & 1) << 2) | (j & 2) | (j >> 2);
}

// 8-point radix-2 DIF FFT in registers. Natural input; reg j holds X[br3(j)].
__device__ __forceinline__ void fft8(float* ar, float* ai)
{
    constexpr float R = 0.70710678118654752f;
    constexpr float C8[4] = { 1.f,  R, 0.f, -R };
    constexpr float S8[4] = { 0.f, -R, -1.f, -R };
    // stage 1: span 4, tw W8^j
#pragma unroll
    for (int j = 0; j < 4; j++) {
        float ur = ar[j], ui = ai[j];
        float vr = ar[j + 4], vi = ai[j + 4];
        ar[j] = ur + vr;  ai[j] = ui + vi;
        float dr = ur - vr, di = ui - vi;
        ar[j + 4] = dr * C8[j] - di * S8[j];
        ai[j + 4] = dr * S8[j] + di * C8[j];
    }
    // stage 2: span 2, tw W4^j = {1, -i}
#pragma unroll
    for (int b = 0; b < 8; b += 4) {
        float ur = ar[b], ui = ai[b];
        float vr = ar[b + 2], vi = ai[b + 2];
        ar[b] = ur + vr;      ai[b] = ui + vi;
        ar[b + 2] = ur - vr;  ai[b + 2] = ui - vi;
        ur = ar[b + 1];  ui = ai[b + 1];
        vr = ar[b + 3];  vi = ai[b + 3];
        ar[b + 1] = ur + vr;  ai[b + 1] = ui + vi;
        float dr = ur - vr, di = ui - vi;   // * (-i)
        ar[b + 3] = di;  ai[b + 3] = -dr;
    }
    // stage 3: span 1
#pragma unroll
    for (int b = 0; b < 8; b += 2) {
        float ur = ar[b], ui = ai[b];
        float vr = ar[b + 1], vi = ai[b + 1];
        ar[b] = ur + vr;      ai[b] = ui + vi;
        ar[b + 1] = ur - vr;  ai[b + 1] = ui - vi;
    }
}

// Two DIF split stages across the lane quad (lane bits 3..4 = h2).
// Lane h2 holds samples n = h2*8 + j of a 32-pt sequence. After both stages +
// fft8, lane h2 reg j holds X32[ 4*br3(j) + 2*(h2&1) + (h2>>1) ].
// Stage-1 odd twiddle W32^(8+j) = -i*W32^j folded as a register swap.
__device__ __forceinline__ void split32_4(float* ar, float* ai, int h2)
{
    constexpr float C32[8] = { 1.f, 0.98078528040323044f, 0.92387953251128674f,
        0.83146961230254524f, 0.70710678118654752f, 0.55557023301960222f,
        0.38268343236508977f, 0.19509032201612827f };
    constexpr float S32[8] = { 0.f, -0.19509032201612827f, -0.38268343236508977f,
       -0.55557023301960222f, -0.70710678118654752f, -0.83146961230254524f,
       -0.92387953251128674f, -0.98078528040323044f };
    constexpr float C16[8] = { 1.f, 0.92387953251128674f, 0.70710678118654752f,
        0.38268343236508977f, 0.f, -0.38268343236508977f,
       -0.70710678118654752f, -0.92387953251128674f };
    constexpr float S16[8] = { 0.f, -0.38268343236508977f, -0.70710678118654752f,
       -0.92387953251128674f, -1.f, -0.92387953251128674f,
       -0.70710678118654752f, -0.38268343236508977f };

    // stage 1: pair n <-> n+16  (lane bit 4)
#pragma unroll
    for (int j = 0; j < 8; j++) {
        float brr = __shfl_xor_sync(0xffffffffu, ar[j], 16);
        float bii = __shfl_xor_sync(0xffffffffu, ai[j], 16);
        if (h2 & 2) {          // odd half: (x[n] - x[n+16]) * W32^n
            float dr = brr - ar[j], di = bii - ai[j];
            float vr = dr * C32[j] - di * S32[j];
            float vi = dr * S32[j] + di * C32[j];
            if (h2 & 1) { float t = vr; vr = vi; vi = -t; }  // * W32^8 = -i
            ar[j] = vr;  ai[j] = vi;
        } else {               // even half: x[n] + x[n+16]
            ar[j] += brr;
            ai[j] += bii;
        }
    }
    // stage 2: pair n <-> n+8 within each 16-group  (lane bit 3)
#pragma unroll
    for (int j = 0; j < 8; j++) {
        float brr = __shfl_xor_sync(0xffffffffu, ar[j], 8);
        float bii = __shfl_xor_sync(0xffffffffu, ai[j], 8);
        if (h2 & 1) {          // odd: (y[j] - y[j+8]) * W16^j
            float dr = brr - ar[j], di = bii - ai[j];
            ar[j] = dr * C16[j] - di * S16[j];
            ai[j] = dr * S16[j] + di * C16[j];
        } else {
            ar[j] += brr;
            ai[j] += bii;
        }
    }
}

// Four-step 1024 = 32 x 32, one row per 128-thread CTA (4 warps).
// Each 32-pt sub-FFT: 2 shfl DIF stages over a lane quad + fft8 in regs.
// Single transposed smem exchange, pitch 34 float2 (phase-B LDS.128
// conflict-free: 2*34 mod 32 == 4 tiles all banks).
__global__ void __launch_bounds__(THREADS, 10) fft1024_kernel(
    const float* __restrict__ xin, float* __restrict__ xout)
{
    __shared__ __align__(16) float2 sz[32 * 34];

    const int tid = threadIdx.x;
    const int w = tid >> 5;          // warp 0..3
    const int l = tid & 31;
    const int h2 = l >> 3;           // quad index 0..3
    const int q = l & 7;
    const int n1 = w * 8 + q;        // column (phase A) / row (phase B)

    const float2* __restrict__ xb =
        reinterpret_cast<const float2*>(xin) + (size_t)blockIdx.x * 1024;
    float2* __restrict__ yb =
        reinterpret_cast<float2*>(xout) + (size_t)blockIdx.x * 1024;

    float ar[8], ai[8];

    // ===== Phase A: 32-pt FFT over n2, column n1 ===========================
#pragma unroll
    for (int j = 0; j < 8; j++) {
        float2 v = __ldcs(&xb[(h2 * 8 + j) * 32 + n1]);
        ar[j] = v.x;
        ai[j] = v.y;
    }
    split32_4(ar, ai, h2);
    fft8(ar, ai);   // reg j -> Y[n1][k1], k1 = 4*br3(j) + 2*(h2&1) + (h2>>1)

    const int cbits = 2 * (h2 & 1) + (h2 >> 1);
#pragma unroll
    for (int j = 0; j < 8; j++) {
        const int k1 = 4 * br3(j) + cbits;
        const float2 wv = TW.v[k1 * 32 + n1];
        float tr, ti;
        cmul_v(tr, ti, ar[j], ai[j], wv.x, wv.y);
        sz[k1 * 34 + n1] = make_float2(tr, ti);
    }
    __syncthreads();

    // ===== Phase B: 32-pt FFT over k1 within row n1 ========================
    {
        const float4* lp4 = reinterpret_cast<const float4*>(&sz[n1 * 34 + h2 * 8]);
#pragma unroll
        for (int i = 0; i < 4; i++) {
            float4 v = lp4[i];
            ar[2 * i]     = v.x;  ai[2 * i]     = v.y;
            ar[2 * i + 1] = v.z;  ai[2 * i + 1] = v.w;
        }
    }
    split32_4(ar, ai, h2);
    fft8(ar, ai);   // reg j -> X[n1 + 32*k2], k2 = 4*br3(j) + cbits

#pragma unroll
    for (int j = 0; j < 8; j++) {
        const int k2 = 4 * br3(j) + cbits;
        __stcs(&yb[n1 + 32 * k2], make_float2(ar[j], ai[j]));
    }
}

extern "C" void kernel_launch(void* const* d_in, const int* in_sizes, int n_in,
                              void* d_out, int out_size)
{
    const float* x = (const float*)d_in[0];
    float* y = (float*)d_out;
    const int B = in_sizes[0] / 2048;   // 1024 complex per row
    fft1024_kernel<<<B, THREADS>>>(x, y);
}

// round 9
// speedup vs baseline: 1.3985x; 1.3985x over previous
#include <cuda_runtime.h>

#define THREADS 64   // one row (1024-pt FFT) per CTA: 2 warps, 32 lane-pairs

// ===================== compile-time twiddle table =======================
// TW[k*32 + n] = exp(-2*pi*i * n*k / 1024), n,k in [0,32).
// Only rows k=0,1,2 are read at runtime (bases Q and V); kept full for clarity.
__host__ __device__ constexpr double tsin_(double x) {
    double t = x, s = x;
    for (int k = 1; k < 13; k++) { t *= -x * x / ((2.0 * k) * (2.0 * k + 1.0)); s += t; }
    return s;
}
__host__ __device__ constexpr double tcos_(double x) {
    double t = 1.0, s = 1.0;
    for (int k = 1; k < 13; k++) { t *= -x * x / ((2.0 * k - 1.0) * (2.0 * k)); s += t; }
    return s;
}
struct alignas(16) TwTab { float2 v[1024]; };
__host__ __device__ constexpr TwTab make_tw_() {
    TwTab t{};
    constexpr double PI = 3.14159265358979323846;
    for (int k = 0; k < 32; k++)
        for (int n = 0; n < 32; n++) {
            double ang = -2.0 * PI * (double)(n * k) / 1024.0;
            if (ang < -PI) ang += 2.0 * PI;
            t.v[k * 32 + n] = float2{ (float)tcos_(ang), (float)tsin_(ang) };
        }
    return t;
}
__device__ const TwTab TW = make_tw_();

__device__ __forceinline__ float2 cmulf(float2 a, float2 b) {
    return make_float2(fmaf(a.x, b.x, -a.y * b.y), fmaf(a.x, b.y, a.y * b.x));
}

// 16-point radix-4 DIF FFT (2 stages). Natural input; reg j holds X[dr4(j)],
// dr4(j) = ((j&3)<<2) | (j>>2).
__device__ __forceinline__ void fft16(float* ar, float* ai)
{
    constexpr float Cq = 0.92387953251128674f;
    constexpr float Sq = 0.38268343236508977f;
    constexpr float Rh = 0.70710678118654752f;
    constexpr float AR[4] = {1.f,  Cq,  Rh,  Sq}, AI[4] = {0.f, -Sq, -Rh, -Cq};
    constexpr float BR[4] = {1.f,  Rh, 0.f, -Rh}, BI[4] = {0.f, -Rh, -1.f, -Rh};
    constexpr float CR[4] = {1.f,  Sq, -Rh, -Cq}, CI[4] = {0.f, -Cq, -Rh,  Sq};

#pragma unroll
    for (int j = 0; j < 4; j++) {
        float t0r = ar[j]   + ar[j+8],  t0i = ai[j]   + ai[j+8];
        float t1r = ar[j]   - ar[j+8],  t1i = ai[j]   - ai[j+8];
        float t2r = ar[j+4] + ar[j+12], t2i = ai[j+4] + ai[j+12];
        float t3r = ai[j+4] - ai[j+12], t3i = ar[j+12] - ar[j+4];
        ar[j] = t0r + t2r;  ai[j] = t0i + t2i;
        float u1r = t1r + t3r, u1i = t1i + t3i;
        float u2r = t0r - t2r, u2i = t0i - t2i;
        float u3r = t1r - t3r, u3i = t1i - t3i;
        ar[j+4]  = u1r*AR[j] - u1i*AI[j];  ai[j+4]  = u1r*AI[j] + u1i*AR[j];
        ar[j+8]  = u2r*BR[j] - u2i*BI[j];  ai[j+8]  = u2r*BI[j] + u2i*BR[j];
        ar[j+12] = u3r*CR[j] - u3i*CI[j];  ai[j+12] = u3r*CI[j] + u3i*CR[j];
    }
#pragma unroll
    for (int g = 0; g < 4; g++) {
        const int b = 4 * g;
        float t0r = ar[b]   + ar[b+2], t0i = ai[b]   + ai[b+2];
        float t1r = ar[b]   - ar[b+2], t1i = ai[b]   - ai[b+2];
        float t2r = ar[b+1] + ar[b+3], t2i = ai[b+1] + ai[b+3];
        float t3r = ai[b+1] - ai[b+3], t3i = ar[b+3] - ar[b+1];
        ar[b]   = t0r + t2r;  ai[b]   = t0i + t2i;
        ar[b+1] = t1r + t3r;  ai[b+1] = t1i + t3i;
        ar[b+2] = t0r - t2r;  ai[b+2] = t0i - t2i;
        ar[b+3] = t1r - t3r;  ai[b+3] = t1i - t3i;
    }
}

__device__ __forceinline__ int dr4(int j) { return ((j & 3) << 2) | (j >> 2); }

// DIF lane-pair split before fft16. Lane h=0 holds x[j], lane h=1 holds
// x[j+16]. After split + fft16: lane h, reg j => X32[2*dr4(j) + h].
// W32^j are compile-time immediates.
__device__ __forceinline__ void dif_split32(float* ar, float* ai, int h)
{
    constexpr float WC[16] = { 1.0f, 0.98078528040323044f, 0.92387953251128674f,
        0.83146961230254524f, 0.70710678118654752f, 0.55557023301960222f,
        0.38268343236508977f, 0.19509032201612827f, 0.0f, -0.19509032201612827f,
       -0.38268343236508977f, -0.55557023301960222f, -0.70710678118654752f,
       -0.83146961230254524f, -0.92387953251128674f, -0.98078528040323044f };
    constexpr float WS[16] = { 0.0f, -0.19509032201612827f, -0.38268343236508977f,
       -0.55557023301960222f, -0.70710678118654752f, -0.83146961230254524f,
       -0.92387953251128674f, -0.98078528040323044f, -1.0f, -0.98078528040323044f,
       -0.92387953251128674f, -0.83146961230254524f, -0.70710678118654752f,
       -0.55557023301960222f, -0.38268343236508977f, -0.19509032201612827f };

#pragma unroll
    for (int j = 0; j < 16; j++) {
        float br = __shfl_xor_sync(0xffffffffu, ar[j], 16);
        float bi = __shfl_xor_sync(0xffffffffu, ai[j], 16);
        if (h) {
            float dr = br - ar[j], di = bi - ai[j];
            ar[j] = dr * WC[j] - di * WS[j];
            ai[j] = dr * WS[j] + di * WC[j];
        } else {
            ar[j] += br;
            ai[j] += bi;
        }
    }
}

// Four-step 1024 = 32 x 32, one row per 64-thread CTA.
// Inter-phase twiddles COMPUTED from two L2-hot bases (Q = W^(h*n1),
// V = W^(2*n1)) via two parallel 7-deep product chains -> no per-element
// table loads, no dependent-LDG stall before the smem stores.
__global__ void __launch_bounds__(THREADS, 16) fft1024_kernel(
    const float* __restrict__ xin, float* __restrict__ xout)
{
    __shared__ __align__(16) float2 sz[32 * 34];

    const int tid = threadIdx.x;     // 0..63
    const int w = tid >> 5;          // warp
    const int l = tid & 31;
    const int h = l >> 4;            // lane-pair half
    const int q = l & 15;
    const int n1 = w * 16 + q;       // column (phase A) / row (phase B)

    // twiddle bases, issued first (independent of data)
    const float2 Q = TW.v[h * 32 + n1];   // W1024^(h*n1)  (k=0 row == 1+0i)
    const float2 V = TW.v[2 * 32 + n1];   // W1024^(2*n1)

    const float2* __restrict__ xb =
        reinterpret_cast<const float2*>(xin) + (size_t)blockIdx.x * 1024;
    float2* __restrict__ yb =
        reinterpret_cast<float2*>(xout) + (size_t)blockIdx.x * 1024;

    float ar[16], ai[16];

    // ===== Phase A: 32-pt FFT over n2, column n1 ===========================
#pragma unroll
    for (int j = 0; j < 16; j++) {
        float2 v = __ldcs(&xb[(h * 16 + j) * 32 + n1]);
        ar[j] = v.x;
        ai[j] = v.y;
    }
    dif_split32(ar, ai, h);
    fft16(ar, ai);          // lane h, reg j -> Y[n1][k1], k1 = 2*dr4(j)+h

    // inter-phase twiddle W1024^(n1*k1) = Q * V^m, where k1 = 2m+h.
    // Two parallel chains: Pa covers m=0..7, Pb covers m=8..15.
    {
        float2 t = cmulf(V, V);
        t = cmulf(t, t);
        const float2 V8 = cmulf(t, t);      // V^8
        float2 Pa = Q;                      // Q * V^0
        float2 Pb = cmulf(Q, V8);           // Q * V^8
#pragma unroll
        for (int m = 0; m < 8; m++) {
            const int ja = dr4(m);          // reg holding k1 = 2m+h
            const int jb = dr4(m + 8);      // reg holding k1 = 2(m+8)+h
            sz[(2 * m + h) * 34 + n1] =
                cmulf(make_float2(ar[ja], ai[ja]), Pa);
            sz[(2 * (m + 8) + h) * 34 + n1] =
                cmulf(make_float2(ar[jb], ai[jb]), Pb);
            if (m < 7) {
                Pa = cmulf(Pa, V);
                Pb = cmulf(Pb, V);
            }
        }
    }
    __syncthreads();

    // ===== Phase B: 32-pt FFT over k1 within row n1 ========================
    // lane h reads contiguous elements h*16..h*16+15 of row n1 -> 8 x LDS.128
    {
        const float4* lp4 = reinterpret_cast<const float4*>(&sz[n1 * 34 + h * 16]);
#pragma unroll
        for (int i = 0; i < 8; i++) {
            float4 v = lp4[i];
            ar[2 * i]     = v.x;  ai[2 * i]     = v.y;
            ar[2 * i + 1] = v.z;  ai[2 * i + 1] = v.w;
        }
    }
    dif_split32(ar, ai, h);
    fft16(ar, ai);          // lane h, reg j -> X[n1 + 32*k2], k2 = 2*dr4(j)+h

#pragma unroll
    for (int j = 0; j < 16; j++) {
        const int k2 = 2 * dr4(j) + h;
        __stcs(&yb[n1 + 32 * k2], make_float2(ar[j], ai[j]));
    }
}

extern "C" void kernel_launch(void* const* d_in, const int* in_sizes, int n_in,
                              void* d_out, int out_size)
{
    const float* x = (const float*)d_in[0];
    float* y = (float*)d_out;
    const int B = in_sizes[0] / 2048;   // 1024 complex per row
    fft1024_kernel<<<B, THREADS>>>(x, y);
}